// round 15
// baseline (speedup 1.0000x reference)
#include <cuda_runtime.h>
#include <math.h>

#define BB 32
#define DIN 1024
#define DOUT 1024
#define BETA 0.9f
#define LEAK 0.9f

#define NTHR 256
#define KTILE 16
#define NSPLIT (DIN / KTILE)   /* 64 */
#define NJT 8                  /* j tiles of 128 columns */

/* output offsets (floats), in reference return order:
   s, E_W2, E_b2, Rh_W2, Rh_b2, g_bar2, r2 */
#define OFF_S  0
#define OFF_EW (BB * DOUT)
#define OFF_EB (OFF_EW + BB * DIN * DOUT)
#define OFF_RW (OFF_EB + BB * DOUT)
#define OFF_RB (OFF_RW + BB * DIN * DOUT)
#define OFF_G  (OFF_RB + BB * DOUT)
#define OFF_R  (OFF_G + BB * DOUT)

__device__ float g_hpart[NSPLIT][BB * DOUT];   /* 8 MB scratch */
__device__ unsigned int g_cnt[NJT];            /* monotonic per-tile counters */

/* ---------- kernel 1: GEMM + (last block per j-tile) epilogue ---------- */
__global__ void __launch_bounds__(NTHR, 4)
fused_prologue(const float* __restrict__ x,
               const float* __restrict__ W,
               const float* __restrict__ bias,
               const float* __restrict__ u,
               const float* __restrict__ E_b,
               const float* __restrict__ Rh_b,
               const float* __restrict__ g_bar,
               const float* __restrict__ r,
               float* __restrict__ out) {
    __shared__ float ws[KTILE][128];   /* 8 KB: W tile 16k x 128j */
    __shared__ float xs[BB][KTILE];    /* 2 KB: x tile 32b x 16k */
    __shared__ int is_last;

    const int bid = blockIdx.x;
    const int tid = threadIdx.x;
    const int jt = bid & 7;
    const int ks = bid >> 3;

    /* ---- Phase A: split-K GEMM tile (jt, ks) ---- */
    {
        const int k0 = ks * KTILE;
        const int jb = jt * 128;

        /* W tile: 512 float4, 2 per thread */
        {
            int f = tid;
            int row = f >> 5, c4 = (f & 31) * 4;
            *(float4*)&ws[row][c4] = *(const float4*)&W[(k0 + row) * DOUT + jb + c4];
            f = tid + 256;
            row = f >> 5; c4 = (f & 31) * 4;
            *(float4*)&ws[row][c4] = *(const float4*)&W[(k0 + row) * DOUT + jb + c4];
        }
        /* x tile: 128 float4, 1 per thread (tid < 128) */
        if (tid < 128) {
            const int bb = tid >> 2;
            const int kq = (tid & 3) * 4;
            const float4 v = *(const float4*)&x[bb * DIN + k0 + kq];
            xs[bb][kq + 0] = v.x;
            xs[bb][kq + 1] = v.y;
            xs[bb][kq + 2] = v.z;
            xs[bb][kq + 3] = v.w;
        }
        __syncthreads();

        const int j4l = (tid & 31) * 4;
        const int bq  = tid >> 5;

        float4 a0 = make_float4(0.f, 0.f, 0.f, 0.f);
        float4 a1 = a0, a2 = a0, a3 = a0;

#pragma unroll
        for (int kk = 0; kk < KTILE; kk++) {
            const float4 w = *(const float4*)&ws[kk][j4l];
            const float x0 = xs[bq * 4 + 0][kk];
            const float x1 = xs[bq * 4 + 1][kk];
            const float x2 = xs[bq * 4 + 2][kk];
            const float x3 = xs[bq * 4 + 3][kk];
            a0.x = fmaf(x0, w.x, a0.x); a0.y = fmaf(x0, w.y, a0.y);
            a0.z = fmaf(x0, w.z, a0.z); a0.w = fmaf(x0, w.w, a0.w);
            a1.x = fmaf(x1, w.x, a1.x); a1.y = fmaf(x1, w.y, a1.y);
            a1.z = fmaf(x1, w.z, a1.z); a1.w = fmaf(x1, w.w, a1.w);
            a2.x = fmaf(x2, w.x, a2.x); a2.y = fmaf(x2, w.y, a2.y);
            a2.z = fmaf(x2, w.z, a2.z); a2.w = fmaf(x2, w.w, a2.w);
            a3.x = fmaf(x3, w.x, a3.x); a3.y = fmaf(x3, w.y, a3.y);
            a3.z = fmaf(x3, w.z, a3.z); a3.w = fmaf(x3, w.w, a3.w);
        }

        float* dst = &g_hpart[ks][0];
        const int jb4 = jt * 128 + j4l;
        *(float4*)&dst[(bq * 4 + 0) * DOUT + jb4] = a0;
        *(float4*)&dst[(bq * 4 + 1) * DOUT + jb4] = a1;
        *(float4*)&dst[(bq * 4 + 2) * DOUT + jb4] = a2;
        *(float4*)&dst[(bq * 4 + 3) * DOUT + jb4] = a3;
    }

    /* ---- completion handoff: last block of this j-tile runs the epilogue */
    __threadfence();
    if (tid == 0) {
        const unsigned int prev = atomicAdd(&g_cnt[jt], 1u);
        is_last = ((prev & (NSPLIT - 1u)) == (NSPLIT - 1u)) ? 1 : 0;
    }
    __syncthreads();
    if (!is_last) return;

    /* ---- Phase B: epilogue for this j-tile (1024 float4 items, 4/thread) */
#pragma unroll
    for (int it = 0; it < 4; it++) {
        const int item = it * 256 + tid;       /* 0..1023 */
        const int bb  = item >> 5;             /* 0..31 */
        const int j4l = item & 31;             /* 0..31 */
        const int j4g = jt * 32 + j4l;         /* 0..255 */
        const int idx4 = bb * 256 + j4g;

        float4 h = ((const float4*)bias)[j4g];
#pragma unroll 8
        for (int kss = 0; kss < NSPLIT; kss++) {
            const float4 p = __ldcg(&((const float4*)g_hpart[kss])[idx4]);
            h.x += p.x; h.y += p.y; h.z += p.z; h.w += p.w;
        }

        const float4 uu = ((const float4*)u)[idx4];
        const float4 eb = ((const float4*)E_b)[idx4];
        const float4 rb = ((const float4*)Rh_b)[idx4];
        const float4 gb = ((const float4*)g_bar)[idx4];

        const float ratio0 = LEAK * r[bb];
        const float r2 = ratio0 + 1.0f;
        const float ratio = ratio0 / r2;

        float4 so, ebo, rbo, go;
        {
            const float un = BETA * uu.x + h.x;
            const float s  = 1.0f / (1.0f + expf(-(un - 1.0f)));
            const float sg = s * (1.0f - s);
            const float a  = BETA * sg;
            so.x = s;
            const float eb1 = BETA * eb.x + 1.0f;
            ebo.x = BETA * eb1 + 1.0f;
            rbo.x = a * rb.x + (a * eb1 + sg);
            go.x  = ratio * gb.x + (1.0f - ratio) * a;
        }
        {
            const float un = BETA * uu.y + h.y;
            const float s  = 1.0f / (1.0f + expf(-(un - 1.0f)));
            const float sg = s * (1.0f - s);
            const float a  = BETA * sg;
            so.y = s;
            const float eb1 = BETA * eb.y + 1.0f;
            ebo.y = BETA * eb1 + 1.0f;
            rbo.y = a * rb.y + (a * eb1 + sg);
            go.y  = ratio * gb.y + (1.0f - ratio) * a;
        }
        {
            const float un = BETA * uu.z + h.z;
            const float s  = 1.0f / (1.0f + expf(-(un - 1.0f)));
            const float sg = s * (1.0f - s);
            const float a  = BETA * sg;
            so.z = s;
            const float eb1 = BETA * eb.z + 1.0f;
            ebo.z = BETA * eb1 + 1.0f;
            rbo.z = a * rb.z + (a * eb1 + sg);
            go.z  = ratio * gb.z + (1.0f - ratio) * a;
        }
        {
            const float un = BETA * uu.w + h.w;
            const float s  = 1.0f / (1.0f + expf(-(un - 1.0f)));
            const float sg = s * (1.0f - s);
            const float a  = BETA * sg;
            so.w = s;
            const float eb1 = BETA * eb.w + 1.0f;
            ebo.w = BETA * eb1 + 1.0f;
            rbo.w = a * rb.w + (a * eb1 + sg);
            go.w  = ratio * gb.w + (1.0f - ratio) * a;
        }

        ((float4*)(out + OFF_S))[idx4]  = so;
        ((float4*)(out + OFF_EB))[idx4] = ebo;
        ((float4*)(out + OFF_RB))[idx4] = rbo;
        ((float4*)(out + OFF_G))[idx4]  = go;
        if (j4g == 0) out[OFF_R + bb] = r2;
    }
}

/* ---------------- kernel 2: big streaming trace update ----------------- */
/* Flat 32768-block launch, one float4 pair per thread — 6.4+ TB/s shape. */
__global__ void __launch_bounds__(256) big_update(const float* __restrict__ x,
                                                  const float4* __restrict__ E_W,
                                                  const float4* __restrict__ Rh_W,
                                                  float* __restrict__ out) {
    const float4* __restrict__ s4p = (const float4*)(out + OFF_S);
    float4* __restrict__ ew2 = (float4*)(out + OFF_EW);
    float4* __restrict__ rw2 = (float4*)(out + OFF_RW);

    const int idx = blockIdx.x * 256 + threadIdx.x;   /* 0..8388607 */
    const int bb  = idx >> 18;
    const int rem = idx & 262143;
    const int i   = rem >> 8;
    const int j4  = rem & 255;

    const float4 ew = __ldcs(&E_W[idx]);
    const float4 rh = __ldcs(&Rh_W[idx]);
    const float  xv = __ldg(&x[bb * DIN + i]);
    const float4 s4 = s4p[bb * 256 + j4];

    float4 o1, o2;

    {
        const float sg = s4.x * (1.0f - s4.x);
        const float a  = BETA * sg;
        const float e1 = fmaf(BETA, ew.x, xv);
        o1.x = fmaf(BETA, e1, xv);
        o2.x = fmaf(a, rh.x, fmaf(a, e1, xv * sg));
    }
    {
        const float sg = s4.y * (1.0f - s4.y);
        const float a  = BETA * sg;
        const float e1 = fmaf(BETA, ew.y, xv);
        o1.y = fmaf(BETA, e1, xv);
        o2.y = fmaf(a, rh.y, fmaf(a, e1, xv * sg));
    }
    {
        const float sg = s4.z * (1.0f - s4.z);
        const float a  = BETA * sg;
        const float e1 = fmaf(BETA, ew.z, xv);
        o1.z = fmaf(BETA, e1, xv);
        o2.z = fmaf(a, rh.z, fmaf(a, e1, xv * sg));
    }
    {
        const float sg = s4.w * (1.0f - s4.w);
        const float a  = BETA * sg;
        const float e1 = fmaf(BETA, ew.w, xv);
        o1.w = fmaf(BETA, e1, xv);
        o2.w = fmaf(a, rh.w, fmaf(a, e1, xv * sg));
    }

    __stcs(&ew2[idx], o1);
    __stcs(&rw2[idx], o2);
}

extern "C" void kernel_launch(void* const* d_in, const int* in_sizes, int n_in,
                              void* d_out, int out_size) {
    const float* x     = (const float*)d_in[0];
    const float* W     = (const float*)d_in[1];
    const float* bias  = (const float*)d_in[2];
    const float* u     = (const float*)d_in[3];
    const float* E_W   = (const float*)d_in[4];
    const float* E_b   = (const float*)d_in[5];
    const float* Rh_W  = (const float*)d_in[6];
    const float* Rh_b  = (const float*)d_in[7];
    const float* g_bar = (const float*)d_in[8];
    const float* r     = (const float*)d_in[9];
    float* out = (float*)d_out;

    fused_prologue<<<NJT * NSPLIT, NTHR>>>(x, W, bias, u, E_b, Rh_b, g_bar, r, out);
    big_update<<<(BB * DIN * DOUT / 4) / 256, 256>>>(x, (const float4*)E_W,
                                                     (const float4*)Rh_W, out);
}

// round 16
// speedup vs baseline: 1.1280x; 1.1280x over previous
#include <cuda_runtime.h>
#include <math.h>

#define BB 32
#define DIN 1024
#define DOUT 1024
#define BETA 0.9f
#define LEAK 0.9f

#define GRIDN 512
#define NTHR 256
#define KTILE 16
#define NSPLIT (DIN / KTILE)   /* 64 */

/* output offsets (floats), in reference return order:
   s, E_W2, E_b2, Rh_W2, Rh_b2, g_bar2, r2 */
#define OFF_S  0
#define OFF_EW (BB * DOUT)
#define OFF_EB (OFF_EW + BB * DIN * DOUT)
#define OFF_RW (OFF_EB + BB * DOUT)
#define OFF_RB (OFF_RW + BB * DIN * DOUT)
#define OFF_G  (OFF_RB + BB * DOUT)
#define OFF_R  (OFF_G + BB * DOUT)

__device__ float g_hpart[NSPLIT][BB * DOUT];   /* 8 MB scratch */
__device__ unsigned int g_c1;                  /* monotonic barrier counter */

/* wrap-safe, reset-free grid barrier (2^32 % 512 == 0). */
__device__ __forceinline__ void grid_sync(unsigned int* cnt) {
    __syncthreads();
    if (threadIdx.x == 0) {
        __threadfence();
        const unsigned int prev = atomicAdd(cnt, 1u);
        const unsigned int target = prev - (prev % GRIDN) + GRIDN;
        volatile unsigned int* vc = (volatile unsigned int*)cnt;
        while ((int)(*vc - target) < 0) { __nanosleep(64); }
        __threadfence();
    }
    __syncthreads();
}

/* ---------- kernel 1: fused GEMM + activation + small outputs ---------- */
__global__ void __launch_bounds__(NTHR, 4)
fused_prologue(const float* __restrict__ x,
               const float* __restrict__ W,
               const float* __restrict__ bias,
               const float* __restrict__ u,
               const float* __restrict__ E_b,
               const float* __restrict__ Rh_b,
               const float* __restrict__ g_bar,
               const float* __restrict__ r,
               float* __restrict__ out) {
    __shared__ float ws[KTILE][128];   /* 8 KB: W tile 16k x 128j */
    __shared__ float xs[BB][KTILE];    /* 2 KB: x tile 32b x 16k */

    /* release the PDL latch immediately: all our CTAs are placed, so the
       dependent big_update grid may start prefetching its streams now */
    if (threadIdx.x == 0) cudaTriggerProgrammaticLaunchCompletion();

    const int bid = blockIdx.x;
    const int tid = threadIdx.x;

    /* ---- Phase A: split-K GEMM, (jt, ks) = (8 x 64) over 512 blocks ---- */
    {
        const int jt = bid & 7;
        const int ks = bid >> 3;
        const int k0 = ks * KTILE;
        const int jb = jt * 128;

        /* W tile: 512 float4, 2 per thread */
        {
            int f = tid;
            int row = f >> 5, c4 = (f & 31) * 4;
            *(float4*)&ws[row][c4] = *(const float4*)&W[(k0 + row) * DOUT + jb + c4];
            f = tid + 256;
            row = f >> 5; c4 = (f & 31) * 4;
            *(float4*)&ws[row][c4] = *(const float4*)&W[(k0 + row) * DOUT + jb + c4];
        }
        /* x tile: 128 float4, 1 per thread (tid < 128) */
        if (tid < 128) {
            const int bb = tid >> 2;
            const int kq = (tid & 3) * 4;
            const float4 v = *(const float4*)&x[bb * DIN + k0 + kq];
            xs[bb][kq + 0] = v.x;
            xs[bb][kq + 1] = v.y;
            xs[bb][kq + 2] = v.z;
            xs[bb][kq + 3] = v.w;
        }
        __syncthreads();

        const int j4l = (tid & 31) * 4;
        const int bq  = tid >> 5;

        float4 a0 = make_float4(0.f, 0.f, 0.f, 0.f);
        float4 a1 = a0, a2 = a0, a3 = a0;

#pragma unroll
        for (int kk = 0; kk < KTILE; kk++) {
            const float4 w = *(const float4*)&ws[kk][j4l];
            const float x0 = xs[bq * 4 + 0][kk];
            const float x1 = xs[bq * 4 + 1][kk];
            const float x2 = xs[bq * 4 + 2][kk];
            const float x3 = xs[bq * 4 + 3][kk];
            a0.x = fmaf(x0, w.x, a0.x); a0.y = fmaf(x0, w.y, a0.y);
            a0.z = fmaf(x0, w.z, a0.z); a0.w = fmaf(x0, w.w, a0.w);
            a1.x = fmaf(x1, w.x, a1.x); a1.y = fmaf(x1, w.y, a1.y);
            a1.z = fmaf(x1, w.z, a1.z); a1.w = fmaf(x1, w.w, a1.w);
            a2.x = fmaf(x2, w.x, a2.x); a2.y = fmaf(x2, w.y, a2.y);
            a2.z = fmaf(x2, w.z, a2.z); a2.w = fmaf(x2, w.w, a2.w);
            a3.x = fmaf(x3, w.x, a3.x); a3.y = fmaf(x3, w.y, a3.y);
            a3.z = fmaf(x3, w.z, a3.z); a3.w = fmaf(x3, w.w, a3.w);
        }

        float* dst = &g_hpart[ks][0];
        const int jb4 = jb + j4l;
        *(float4*)&dst[(bq * 4 + 0) * DOUT + jb4] = a0;
        *(float4*)&dst[(bq * 4 + 1) * DOUT + jb4] = a1;
        *(float4*)&dst[(bq * 4 + 2) * DOUT + jb4] = a2;
        *(float4*)&dst[(bq * 4 + 3) * DOUT + jb4] = a3;
    }

    grid_sync(&g_c1);

    /* ---- Phase B: activation + small outputs (16 float4 items/block) ---- */
    if (tid < 16) {
        const int idx4 = bid * 16 + tid;      /* 0..8191 */
        const int bb = idx4 >> 8;
        const int j4 = idx4 & 255;

        float4 h = ((const float4*)bias)[j4];
#pragma unroll 8
        for (int ks = 0; ks < NSPLIT; ks++) {
            const float4 p = __ldcg(&((const float4*)g_hpart[ks])[idx4]);
            h.x += p.x; h.y += p.y; h.z += p.z; h.w += p.w;
        }

        const float4 uu = ((const float4*)u)[idx4];
        const float4 eb = ((const float4*)E_b)[idx4];
        const float4 rb = ((const float4*)Rh_b)[idx4];
        const float4 gb = ((const float4*)g_bar)[idx4];

        const float ratio0 = LEAK * r[bb];
        const float r2 = ratio0 + 1.0f;
        const float ratio = ratio0 / r2;

        float4 so, ebo, rbo, go;
        {
            const float un = BETA * uu.x + h.x;
            const float s  = 1.0f / (1.0f + expf(-(un - 1.0f)));
            const float sg = s * (1.0f - s);
            const float a  = BETA * sg;
            so.x = s;
            const float eb1 = BETA * eb.x + 1.0f;
            ebo.x = BETA * eb1 + 1.0f;
            rbo.x = a * rb.x + (a * eb1 + sg);
            go.x  = ratio * gb.x + (1.0f - ratio) * a;
        }
        {
            const float un = BETA * uu.y + h.y;
            const float s  = 1.0f / (1.0f + expf(-(un - 1.0f)));
            const float sg = s * (1.0f - s);
            const float a  = BETA * sg;
            so.y = s;
            const float eb1 = BETA * eb.y + 1.0f;
            ebo.y = BETA * eb1 + 1.0f;
            rbo.y = a * rb.y + (a * eb1 + sg);
            go.y  = ratio * gb.y + (1.0f - ratio) * a;
        }
        {
            const float un = BETA * uu.z + h.z;
            const float s  = 1.0f / (1.0f + expf(-(un - 1.0f)));
            const float sg = s * (1.0f - s);
            const float a  = BETA * sg;
            so.z = s;
            const float eb1 = BETA * eb.z + 1.0f;
            ebo.z = BETA * eb1 + 1.0f;
            rbo.z = a * rb.z + (a * eb1 + sg);
            go.z  = ratio * gb.z + (1.0f - ratio) * a;
        }
        {
            const float un = BETA * uu.w + h.w;
            const float s  = 1.0f / (1.0f + expf(-(un - 1.0f)));
            const float sg = s * (1.0f - s);
            const float a  = BETA * sg;
            so.w = s;
            const float eb1 = BETA * eb.w + 1.0f;
            ebo.w = BETA * eb1 + 1.0f;
            rbo.w = a * rb.w + (a * eb1 + sg);
            go.w  = ratio * gb.w + (1.0f - ratio) * a;
        }

        ((float4*)(out + OFF_S))[idx4]  = so;
        ((float4*)(out + OFF_EB))[idx4] = ebo;
        ((float4*)(out + OFF_RB))[idx4] = rbo;
        ((float4*)(out + OFF_G))[idx4]  = go;
        if (j4 == 0) out[OFF_R + bb] = r2;
    }
}

/* ---------------- kernel 2: big streaming trace update (PDL) ----------- */
/* Launched with programmatic stream serialization: blocks start during the
   prologue, issue their independent DRAM stream loads, THEN wait on the
   prologue grid before touching s. */
__global__ void __launch_bounds__(256) big_update(const float* __restrict__ x,
                                                  const float4* __restrict__ E_W,
                                                  const float4* __restrict__ Rh_W,
                                                  float* __restrict__ out) {
    const float4* __restrict__ s4p = (const float4*)(out + OFF_S);
    float4* __restrict__ ew2 = (float4*)(out + OFF_EW);
    float4* __restrict__ rw2 = (float4*)(out + OFF_RW);

    const int idx = blockIdx.x * 256 + threadIdx.x;   /* 0..8388607 */
    const int bb  = idx >> 18;
    const int rem = idx & 262143;
    const int i   = rem >> 8;
    const int j4  = rem & 255;

    /* prologue-independent loads first — overlap with K1 */
    const float4 ew = __ldcs(&E_W[idx]);
    const float4 rh = __ldcs(&Rh_W[idx]);
    const float  xv = __ldg(&x[bb * DIN + i]);

    /* wait for fused_prologue grid completion (s is now valid) */
    cudaGridDependencySynchronize();

    const float4 s4 = s4p[bb * 256 + j4];

    float4 o1, o2;

    {
        const float sg = s4.x * (1.0f - s4.x);
        const float a  = BETA * sg;
        const float e1 = fmaf(BETA, ew.x, xv);
        o1.x = fmaf(BETA, e1, xv);
        o2.x = fmaf(a, rh.x, fmaf(a, e1, xv * sg));
    }
    {
        const float sg = s4.y * (1.0f - s4.y);
        const float a  = BETA * sg;
        const float e1 = fmaf(BETA, ew.y, xv);
        o1.y = fmaf(BETA, e1, xv);
        o2.y = fmaf(a, rh.y, fmaf(a, e1, xv * sg));
    }
    {
        const float sg = s4.z * (1.0f - s4.z);
        const float a  = BETA * sg;
        const float e1 = fmaf(BETA, ew.z, xv);
        o1.z = fmaf(BETA, e1, xv);
        o2.z = fmaf(a, rh.z, fmaf(a, e1, xv * sg));
    }
    {
        const float sg = s4.w * (1.0f - s4.w);
        const float a  = BETA * sg;
        const float e1 = fmaf(BETA, ew.w, xv);
        o1.w = fmaf(BETA, e1, xv);
        o2.w = fmaf(a, rh.w, fmaf(a, e1, xv * sg));
    }

    __stcs(&ew2[idx], o1);
    __stcs(&rw2[idx], o2);
}

extern "C" void kernel_launch(void* const* d_in, const int* in_sizes, int n_in,
                              void* d_out, int out_size) {
    const float* x     = (const float*)d_in[0];
    const float* W     = (const float*)d_in[1];
    const float* bias  = (const float*)d_in[2];
    const float* u     = (const float*)d_in[3];
    const float* E_W   = (const float*)d_in[4];
    const float* E_b   = (const float*)d_in[5];
    const float* Rh_W  = (const float*)d_in[6];
    const float* Rh_b  = (const float*)d_in[7];
    const float* g_bar = (const float*)d_in[8];
    const float* r     = (const float*)d_in[9];
    float* out = (float*)d_out;

    fused_prologue<<<GRIDN, NTHR>>>(x, W, bias, u, E_b, Rh_b, g_bar, r, out);

    /* big_update with programmatic dependent launch */
    cudaLaunchConfig_t cfg = {};
    cfg.gridDim  = dim3((BB * DIN * DOUT / 4) / 256, 1, 1);
    cfg.blockDim = dim3(256, 1, 1);
    cfg.dynamicSmemBytes = 0;
    cfg.stream = 0;
    cudaLaunchAttribute attr[1];
    attr[0].id = cudaLaunchAttributeProgrammaticStreamSerialization;
    attr[0].val.programmaticStreamSerializationAllowed = 1;
    cfg.attrs = attr;
    cfg.numAttrs = 1;
    cudaLaunchKernelEx(&cfg, big_update, x, (const float4*)E_W,
                       (const float4*)Rh_W, (float*)out);
}